// round 15
// baseline (speedup 1.0000x reference)
#include <cuda_runtime.h>
#include <math.h>

#define NB   8
#define NDIM 64
#define NH   128
#define NW   128
#define NPIX (NH * NW)     // 16384
#define NC2  256
#define NHID 128

// Global scratch
__device__ float g_u[(size_t)NB * NC2 * NPIX];    // project_in output
__device__ float g_g[(size_t)NB * NHID * NPIX];   // gated output
__device__ float g_Wt1[4 * 64 * 64];              // W_in  transposed: [tile][k][c]
__device__ float g_Wt3[2 * 64 * 64];              // W_out transposed: [kchunk][k][o]

// ---- packed fp32x2 helpers ----
__device__ __forceinline__ unsigned long long pk2(float v) {
    unsigned long long r;
    asm("mov.b64 %0, {%1, %1};" : "=l"(r) : "f"(v));
    return r;
}
__device__ __forceinline__ void fma2(unsigned long long& d, unsigned long long a,
                                     unsigned long long b) {
    asm("fma.rn.f32x2 %0, %1, %2, %0;" : "+l"(d) : "l"(a), "l"(b));
}
__device__ __forceinline__ float2 up2(unsigned long long v) {
    float2 f;
    asm("mov.b64 {%0, %1}, %2;" : "=f"(f.x), "=f"(f.y) : "l"(v));
    return f;
}

// ============================================================================
// K0: transpose weights into [k][c] layout (non-duplicated)
// ============================================================================
__global__ void k_prep(const float* __restrict__ W_in,
                       const float* __restrict__ W_out) {
    int t = blockIdx.x * 256 + threadIdx.x;
    if (t < 4 * 64 * 64) {                       // g_Wt1[tile][k][c]
        int tile = t >> 12, c = (t >> 6) & 63, k = t & 63;
        g_Wt1[(size_t)tile * 4096 + k * 64 + c] = W_in[(tile * 64 + c) * 64 + k];
    }
    if (t < 2 * 64 * 64) {                       // g_Wt3[kc][kk][o]
        int kc = t >> 12, o = (t >> 6) & 63, kk = t & 63;
        g_Wt3[(size_t)kc * 4096 + kk * 64 + o] = W_out[o * 128 + kc * 64 + kk];
    }
}

// ============================================================================
// GEMM inner step: 8 ch (4 packed pairs) x 8 px, channel-packed accumulators.
// Per k: 2 broadcast LDS.128 (w) + 2 LDS.128 (x) + 8 dup-MOVs + 32 FFMA2.
// ============================================================================
#define GEMM_K_STEP(wb, xp, stride, k, acc)                                    \
    {                                                                          \
        const ulonglong2* wp_ = (const ulonglong2*)((wb) + (k) * 64);          \
        ulonglong2 wA_ = wp_[0], wB_ = wp_[1];                                 \
        float4 xv0_ = *(const float4*)((xp) + (k) * (stride));                 \
        float4 xv1_ = *(const float4*)((xp) + (k) * (stride) + 4);             \
        unsigned long long x0_ = pk2(xv0_.x), x1_ = pk2(xv0_.y);               \
        unsigned long long x2_ = pk2(xv0_.z), x3_ = pk2(xv0_.w);               \
        unsigned long long x4_ = pk2(xv1_.x), x5_ = pk2(xv1_.y);               \
        unsigned long long x6_ = pk2(xv1_.z), x7_ = pk2(xv1_.w);               \
        fma2(acc[0][0], wA_.x, x0_); fma2(acc[0][1], wA_.x, x1_);              \
        fma2(acc[0][2], wA_.x, x2_); fma2(acc[0][3], wA_.x, x3_);              \
        fma2(acc[0][4], wA_.x, x4_); fma2(acc[0][5], wA_.x, x5_);              \
        fma2(acc[0][6], wA_.x, x6_); fma2(acc[0][7], wA_.x, x7_);              \
        fma2(acc[1][0], wA_.y, x0_); fma2(acc[1][1], wA_.y, x1_);              \
        fma2(acc[1][2], wA_.y, x2_); fma2(acc[1][3], wA_.y, x3_);              \
        fma2(acc[1][4], wA_.y, x4_); fma2(acc[1][5], wA_.y, x5_);              \
        fma2(acc[1][6], wA_.y, x6_); fma2(acc[1][7], wA_.y, x7_);              \
        fma2(acc[2][0], wB_.x, x0_); fma2(acc[2][1], wB_.x, x1_);              \
        fma2(acc[2][2], wB_.x, x2_); fma2(acc[2][3], wB_.x, x3_);              \
        fma2(acc[2][4], wB_.x, x4_); fma2(acc[2][5], wB_.x, x5_);              \
        fma2(acc[2][6], wB_.x, x6_); fma2(acc[2][7], wB_.x, x7_);              \
        fma2(acc[3][0], wB_.y, x0_); fma2(acc[3][1], wB_.y, x1_);              \
        fma2(acc[3][2], wB_.y, x2_); fma2(acc[3][3], wB_.y, x3_);              \
        fma2(acc[3][4], wB_.y, x4_); fma2(acc[3][5], wB_.y, x5_);              \
        fma2(acc[3][6], wB_.y, x6_); fma2(acc[3][7], wB_.y, x7_);              \
    }

// ============================================================================
// K1: project_in  u[b][c][p] = sum_k W_in[c][k] * x[b][k][p]
// Tile: 64 ch x 256 px, K=64. 256 threads; thread tile 8 ch x 8 px.
// smem 80KB -> 2 blocks/SM.
// ============================================================================
__global__ __launch_bounds__(256)
void k_proj_in(const float* __restrict__ x) {
    extern __shared__ float sm[];
    float* Wt = sm;            // [k=64][c=64]   16KB
    float* Xs = sm + 4096;     // [k=64][p=256]  64KB

    const int p0  = blockIdx.x * 256;
    const int ct  = blockIdx.y;
    const int b   = blockIdx.z;
    const int tid = threadIdx.x;

    const float4* ws = (const float4*)(g_Wt1 + (size_t)ct * 4096);
    for (int l = tid; l < 1024; l += 256) ((float4*)Wt)[l] = ws[l];
    const float* xb = x + (size_t)b * NDIM * NPIX + p0;
    for (int l = tid; l < 64 * 64; l += 256) {
        int k = l >> 6, p4 = l & 63;
        ((float4*)(Xs + k * 256))[p4] = ((const float4*)(xb + (size_t)k * NPIX))[p4];
    }
    __syncthreads();

    const int pg = (tid & 31) * 8;   // 8 px / thread
    const int cg = (tid >> 5) * 8;   // 8 ch / thread (warp-uniform)

    unsigned long long acc[4][8];    // [ch-pair][px]
#pragma unroll
    for (int i = 0; i < 4; i++)
#pragma unroll
        for (int j = 0; j < 8; j++) acc[i][j] = 0ULL;

    const float* wb = Wt + cg;
    const float* xp = Xs + pg;

#pragma unroll 2
    for (int k = 0; k < 64; k++) {
        GEMM_K_STEP(wb, xp, 256, k, acc)
    }

    float* ub = g_u + ((size_t)(b * NC2 + ct * 64 + cg)) * NPIX + p0 + pg;
#pragma unroll
    for (int j = 0; j < 4; j++) {
        float2 v0 = up2(acc[j][0]), v1 = up2(acc[j][1]);
        float2 v2 = up2(acc[j][2]), v3 = up2(acc[j][3]);
        float2 v4 = up2(acc[j][4]), v5 = up2(acc[j][5]);
        float2 v6 = up2(acc[j][6]), v7 = up2(acc[j][7]);
        float* rlo = ub + (size_t)(2 * j) * NPIX;
        float* rhi = ub + (size_t)(2 * j + 1) * NPIX;
        *(float4*)(rlo)     = make_float4(v0.x, v1.x, v2.x, v3.x);
        *(float4*)(rlo + 4) = make_float4(v4.x, v5.x, v6.x, v7.x);
        *(float4*)(rhi)     = make_float4(v0.y, v1.y, v2.y, v3.y);
        *(float4*)(rhi + 4) = make_float4(v4.y, v5.y, v6.y, v7.y);
    }
}

// ============================================================================
// K2: dynamic depthwise 3x3 (SAME) + exact-erf GELU gate
// 32 output rows per block, padded smem rows (stride 136).
// ============================================================================
#define SROW 136
__global__ __launch_bounds__(256)
void k_dwgate(const float* __restrict__ gen, const float* __restrict__ dwk,
              const float* __restrict__ lam) {
    __shared__ float s1[34 * SROW];
    __shared__ float s2[34 * SROW];

    const int r0  = blockIdx.x * 32;
    const int c   = blockIdx.y;
    const int b   = blockIdx.z;
    const int tid = threadIdx.x;

    float kk1[9], kk2[9];
    const float l1 = lam[c], l2 = lam[c + 128];
#pragma unroll
    for (int j = 0; j < 9; j++) {
        kk1[j] = dwk[c * 9 + j]         + l1 * gen[((size_t)b * NC2 + c) * 9 + j];
        kk2[j] = dwk[(c + 128) * 9 + j] + l2 * gen[((size_t)b * NC2 + c + 128) * 9 + j];
    }

    const float* u1 = g_u + ((size_t)b * NC2 + c) * NPIX;
    const float* u2 = u1 + (size_t)NHID * NPIX;

    for (int l = tid; l < 34 * 32; l += 256) {
        int rr = l >> 5, p4 = l & 31;
        int gy = r0 + rr - 1;
        float4 a  = make_float4(0.f, 0.f, 0.f, 0.f);
        float4 bb = a;
        if (gy >= 0 && gy < NH) {
            a  = ((const float4*)(u1 + (size_t)gy * NW))[p4];
            bb = ((const float4*)(u2 + (size_t)gy * NW))[p4];
        }
        ((float4*)(s1 + rr * SROW + 4))[p4] = a;
        ((float4*)(s2 + rr * SROW + 4))[p4] = bb;
    }
    if (tid < 68) {   // zero halo columns (x=-1 -> col 3, x=128 -> col 132)
        int rr = tid >> 1, col = (tid & 1) ? 132 : 3;
        s1[rr * SROW + col] = 0.f;
        s2[rr * SROW + col] = 0.f;
    }
    __syncthreads();

    float* gp = g_g + ((size_t)b * NHID + c) * NPIX + (size_t)r0 * NW;
#pragma unroll
    for (int i = 0; i < 16; i++) {
        int lp = tid + i * 256;
        int lr = lp >> 7;
        int xx = lp & 127;
        float a1 = 0.f, a2 = 0.f;
#pragma unroll
        for (int ky = 0; ky < 3; ky++) {
            const float* r1 = s1 + (lr + ky) * SROW + 4 + xx;
            const float* r2 = s2 + (lr + ky) * SROW + 4 + xx;
            a1 += kk1[ky * 3 + 0] * r1[-1] + kk1[ky * 3 + 1] * r1[0] + kk1[ky * 3 + 2] * r1[1];
            a2 += kk2[ky * 3 + 0] * r2[-1] + kk2[ky * 3 + 1] * r2[0] + kk2[ky * 3 + 2] * r2[1];
        }
        float ge = 0.5f * a1 * (1.0f + erff(a1 * 0.7071067811865475f));
        gp[lp] = ge * a2;
    }
}

// ============================================================================
// K3: project_out  out[b][o][p] = sum_c W_out[o][c] * g[b][c][p]
// Tile: 64 out x 256 px, K=128 in two 64-chunks. 8 ch x 8 px thread tile.
// smem 80KB -> 2 blocks/SM.
// ============================================================================
__global__ __launch_bounds__(256)
void k_proj_out(float* __restrict__ out) {
    extern __shared__ float sm[];
    float* Wt = sm;            // [k=64][o=64] per chunk  16KB
    float* Xs = sm + 4096;     // [k=64][p=256]           64KB

    const int p0  = blockIdx.x * 256;
    const int b   = blockIdx.y;
    const int tid = threadIdx.x;

    const int pg = (tid & 31) * 8;
    const int og = (tid >> 5) * 8;

    unsigned long long acc[4][8];
#pragma unroll
    for (int i = 0; i < 4; i++)
#pragma unroll
        for (int j = 0; j < 8; j++) acc[i][j] = 0ULL;

    const float* wb = Wt + og;
    const float* xp = Xs + pg;

    for (int kc = 0; kc < 2; kc++) {
        const float4* ws = (const float4*)(g_Wt3 + (size_t)kc * 4096);
        for (int l = tid; l < 1024; l += 256) ((float4*)Wt)[l] = ws[l];
        const float* gb = g_g + ((size_t)b * NHID + kc * 64) * NPIX + p0;
        for (int l = tid; l < 64 * 64; l += 256) {
            int k = l >> 6, p4 = l & 63;
            ((float4*)(Xs + k * 256))[p4] =
                ((const float4*)(gb + (size_t)k * NPIX))[p4];
        }
        __syncthreads();

#pragma unroll 2
        for (int k = 0; k < 64; k++) {
            GEMM_K_STEP(wb, xp, 256, k, acc)
        }
        __syncthreads();
    }

    float* ob = out + ((size_t)(b * NDIM + og)) * NPIX + p0 + pg;
#pragma unroll
    for (int j = 0; j < 4; j++) {
        float2 v0 = up2(acc[j][0]), v1 = up2(acc[j][1]);
        float2 v2 = up2(acc[j][2]), v3 = up2(acc[j][3]);
        float2 v4 = up2(acc[j][4]), v5 = up2(acc[j][5]);
        float2 v6 = up2(acc[j][6]), v7 = up2(acc[j][7]);
        float* rlo = ob + (size_t)(2 * j) * NPIX;
        float* rhi = ob + (size_t)(2 * j + 1) * NPIX;
        *(float4*)(rlo)     = make_float4(v0.x, v1.x, v2.x, v3.x);
        *(float4*)(rlo + 4) = make_float4(v4.x, v5.x, v6.x, v7.x);
        *(float4*)(rhi)     = make_float4(v0.y, v1.y, v2.y, v3.y);
        *(float4*)(rhi + 4) = make_float4(v4.y, v5.y, v6.y, v7.y);
    }
}

// ============================================================================
extern "C" void kernel_launch(void* const* d_in, const int* in_sizes, int n_in,
                              void* d_out, int out_size) {
    const float* x     = (const float*)d_in[0];
    const float* gen   = (const float*)d_in[1];
    const float* W_in  = (const float*)d_in[2];
    const float* dwk   = (const float*)d_in[3];
    const float* lam   = (const float*)d_in[4];
    const float* W_out = (const float*)d_in[5];
    float* out = (float*)d_out;

    const int smem = 80 * 1024;
    cudaFuncSetAttribute(k_proj_in,  cudaFuncAttributeMaxDynamicSharedMemorySize, smem);
    cudaFuncSetAttribute(k_proj_out, cudaFuncAttributeMaxDynamicSharedMemorySize, smem);

    k_prep<<<64, 256>>>(W_in, W_out);
    k_proj_in<<<dim3(NPIX / 256, NC2 / 64, NB), 256, smem>>>(x);
    k_dwgate<<<dim3(NH / 32, NHID, NB), 256>>>(gen, dwk, lam);
    k_proj_out<<<dim3(NPIX / 256, NB), 256, smem>>>(out);
}